// round 14
// baseline (speedup 1.0000x reference)
#include <cuda_runtime.h>
#include <math.h>

// ---- static problem dims ----
#define BN      64      // batch (nodes)
#define NCL     128
#define NC      512     // total channels
#define REP     2048    // rep components
#define DD      512     // folded dim
#define NORM_EPS 1e-2f
#define BN_EPS   1e-5f

__device__ __constant__ int REP_OFF_C[4] = {0, 128, 512, 1152};

// ---- scratch (__device__ globals: allocation-free) ----
__device__ float g_s[BN * REP];      // gauge tensor
__device__ float norm_s[BN * NC];    // per-(l,channel) norms
__device__ float nbn_s[BN * NC];     // batchnormed norms
__device__ float h_s[BN * NC];       // MLP hidden
__device__ float n1_s[BN * NC];      // MLP out
__device__ float partN_s[BN][8][4];  // per-node per-segment bilinear partials
__device__ float M2_s[BN][16];       // per-n gated 4x4

// ============================================================
// L2 prefetch of x2d rows that k_reduce reads FIRST.
// Row set: p with (p&7) in {0,1,2}  (= r=0..2 of each warp's 8 rows),
// 192 rows/node * 64 nodes = 12288 rows = 96 MB, split in 3 launches
// (P=0,1,2) of 4096 rows. prefetch.global.L2 has no register result,
// so issuing threads don't wait on data; requests drain at DRAM rate
// while the host kernel's compute blocks run.
// ============================================================
__device__ __forceinline__ void l2_prefetch_rows(const float* x2d, int P,
                                                 int blk, int rowsPerBlk) {
    int tid = threadIdx.x;                    // 256 threads: 4 rows x 64 lines
    int base = P * 4096 + blk * rowsPerBlk;
    for (int i0 = 0; i0 < rowsPerBlk; i0 += 4) {
        int id = base + i0 + (tid >> 6);
        int n = id / 192;
        int rem = id - n * 192;
        int p = (rem / 3) * 8 + (rem % 3);    // (p&7) in {0,1,2}
        const char* a = (const char*)x2d +
            ((size_t)n * 512 + (size_t)p) * 8192 + (size_t)(tid & 63) * 128;
        asm volatile("prefetch.global.L2 [%0];" :: "l"(a));
    }
}

// ============================================================
// K1: per-node norms + gauge tensor.  One block per n.  (R9 proven)
// ============================================================
__global__ void k_norm_gauge(const float* __restrict__ x1d) {
    int n = blockIdx.x;
    __shared__ float xs[REP];   // 8 KB
    __shared__ float ns[NC];    // 2 KB
    const float* xr = x1d + n * REP;
    for (int i = threadIdx.x; i < REP; i += 256) xs[i] = xr[i];
    __syncthreads();
    for (int c = threadIdx.x; c < NC; c += 256) {
        int l = c >> 7, j = c & 127, off = REP_OFF_C[l], nm = 2 * l + 1;
        float s = 0.f;
        #pragma unroll 7
        for (int m = 0; m < nm; m++) { float v = xs[off + m * 128 + j]; s += v * v; }
        float nv = sqrtf(s);
        ns[c] = nv;
        norm_s[n * NC + c] = nv;
    }
    __syncthreads();
    for (int r = threadIdx.x; r < REP; r += 256) {
        int l = (r < 128) ? 0 : (r < 512) ? 1 : (r < 1152) ? 2 : 3;
        int c = l * 128 + ((r - REP_OFF_C[l]) & 127);
        g_s[n * REP + r] = xs[r] / (ns[c] + NORM_EPS);
    }
}

// ============================================================
// K2: batchnorm over batch axis. grid 4 x 128 threads.  (R9 proven)
// ============================================================
__global__ void k_bn() {
    int c = blockIdx.x * 128 + threadIdx.x;
    float mu = 0.f;
    #pragma unroll 8
    for (int n = 0; n < BN; n++) mu += norm_s[n * NC + c];
    mu *= (1.f / BN);
    float var = 0.f;
    #pragma unroll 8
    for (int n = 0; n < BN; n++) { float d = norm_s[n * NC + c] - mu; var += d * d; }
    var *= (1.f / BN);
    float inv = 1.f / sqrtf(var + BN_EPS);
    #pragma unroll 8
    for (int n = 0; n < BN; n++) nbn_s[n * NC + c] = (norm_s[n * NC + c] - mu) * inv;
}

// ============================================================
// K3/K4: [64,512] @ W^T + bias, optional swish.  (R9 proven core)
// blockIdx.y == 8 -> 64 ride-along prefetch blocks (64 rows each).
// ============================================================
__global__ void k_gemm(const float* __restrict__ W, const float* __restrict__ bias,
                       int which, const float* __restrict__ x2d, int P) {
    if (blockIdx.y == 8) {                 // prefetch slice, no compute
        l2_prefetch_rows(x2d, P, blockIdx.x, 64);
        return;
    }
    const float* X = which ? h_s : nbn_s;
    float* Y       = which ? n1_s : h_s;
    __shared__ float xs[512][12];   // 24 KB, transposed
    int ng  = blockIdx.y * 8;
    int tid = threadIdx.x, warp = tid >> 5, lane = tid & 31;
    int o = blockIdx.x * 8 + warp;
    for (int i = tid; i < 8 * 512; i += 256) {
        int j = i >> 9, k = i & 511;
        xs[k][j] = X[(ng + j) * NC + k];
    }
    __syncthreads();
    const float* wrow = W + o * NC;
    float a0=0.f,a1=0.f,a2=0.f,a3=0.f,a4=0.f,a5=0.f,a6=0.f,a7=0.f;
    #pragma unroll
    for (int j = 0; j < 16; j++) {
        int k = lane + (j << 5);
        float w = wrow[k];
        float4 xa = *(const float4*)&xs[k][0];
        float4 xb = *(const float4*)&xs[k][4];
        a0 = fmaf(w, xa.x, a0);
        a1 = fmaf(w, xa.y, a1);
        a2 = fmaf(w, xa.z, a2);
        a3 = fmaf(w, xa.w, a3);
        a4 = fmaf(w, xb.x, a4);
        a5 = fmaf(w, xb.y, a5);
        a6 = fmaf(w, xb.z, a6);
        a7 = fmaf(w, xb.w, a7);
    }
    #pragma unroll
    for (int s = 16; s > 0; s >>= 1) {
        a0 += __shfl_xor_sync(0xffffffff, a0, s);
        a1 += __shfl_xor_sync(0xffffffff, a1, s);
        a2 += __shfl_xor_sync(0xffffffff, a2, s);
        a3 += __shfl_xor_sync(0xffffffff, a3, s);
        a4 += __shfl_xor_sync(0xffffffff, a4, s);
        a5 += __shfl_xor_sync(0xffffffff, a5, s);
        a6 += __shfl_xor_sync(0xffffffff, a6, s);
        a7 += __shfl_xor_sync(0xffffffff, a7, s);
    }
    if (lane == 0) {
        float b = bias[o];
        float v[8] = {a0+b, a1+b, a2+b, a3+b, a4+b, a5+b, a6+b, a7+b};
        #pragma unroll
        for (int j = 0; j < 8; j++) {
            float u = v[j];
            if (!which) u = u / (1.f + expf(-u));   // swish
            Y[(ng + j) * NC + o] = u;
        }
    }
}

// ============================================================
// K5: IELin fused with scalar_mul -> x1d_new.  (R9 proven core)
// blockIdx.y == 16 -> 128 ride-along prefetch blocks (32 rows each).
// ============================================================
__global__ void k_ielin(const float* __restrict__ Wie, float* __restrict__ x1dout,
                        const float* __restrict__ x2d) {
    if (blockIdx.y == 16) {                // prefetch slice, no compute
        l2_prefetch_rows(x2d, 2, blockIdx.x, 32);
        return;
    }
    __shared__ float gsT[128][12];  // 6 KB, transposed
    __shared__ int nrow[8], mrow[8];
    int rowbase = blockIdx.x * 8;
    int l, lbase;
    if (rowbase < 64)       { l = 0; lbase = 0; }
    else if (rowbase < 256) { l = 1; lbase = 64; }
    else if (rowbase < 576) { l = 2; lbase = 256; }
    else                    { l = 3; lbase = 576; }
    int nm = 2 * l + 1, off = REP_OFF_C[l];
    int tid = threadIdx.x, warp = tid >> 5, lane = tid & 31;
    if (tid < 8) {
        int rr = rowbase + tid - lbase;
        nrow[tid] = rr / nm;
        mrow[tid] = rr - nrow[tid] * nm;
    }
    __syncthreads();
    for (int idx = tid; idx < 8 * 128; idx += 256) {
        int j = idx >> 7, i = idx & 127;
        gsT[i][j] = g_s[nrow[j] * REP + off + mrow[j] * 128 + i];
    }
    __syncthreads();
    int o = blockIdx.y * 8 + warp;
    const float* wrow = Wie + (l * 128 + o) * 128;
    float a0=0.f,a1=0.f,a2=0.f,a3=0.f,a4=0.f,a5=0.f,a6=0.f,a7=0.f;
    #pragma unroll
    for (int j = 0; j < 4; j++) {
        int k = lane + (j << 5);
        float w = wrow[k];
        float4 ga = *(const float4*)&gsT[k][0];
        float4 gb = *(const float4*)&gsT[k][4];
        a0 = fmaf(w, ga.x, a0);
        a1 = fmaf(w, ga.y, a1);
        a2 = fmaf(w, ga.z, a2);
        a3 = fmaf(w, ga.w, a3);
        a4 = fmaf(w, gb.x, a4);
        a5 = fmaf(w, gb.y, a5);
        a6 = fmaf(w, gb.z, a6);
        a7 = fmaf(w, gb.w, a7);
    }
    #pragma unroll
    for (int s = 16; s > 0; s >>= 1) {
        a0 += __shfl_xor_sync(0xffffffff, a0, s);
        a1 += __shfl_xor_sync(0xffffffff, a1, s);
        a2 += __shfl_xor_sync(0xffffffff, a2, s);
        a3 += __shfl_xor_sync(0xffffffff, a3, s);
        a4 += __shfl_xor_sync(0xffffffff, a4, s);
        a5 += __shfl_xor_sync(0xffffffff, a5, s);
        a6 += __shfl_xor_sync(0xffffffff, a6, s);
        a7 += __shfl_xor_sync(0xffffffff, a7, s);
    }
    if (lane == 0) {
        float acc[8] = {a0, a1, a2, a3, a4, a5, a6, a7};
        #pragma unroll
        for (int j = 0; j < 8; j++) {
            int n = nrow[j];
            x1dout[n * REP + off + mrow[j] * 128 + o] =
                acc[j] * n1_s[n * NC + l * 128 + o];
        }
    }
}

// ============================================================
// K6: bilinear reduction.  (R9 proven: 512 blocks, 8 segs, r ascending
// -> first reads r=0..2 are the prefetched rows.)
// ============================================================
__global__ void __launch_bounds__(256, 4)
k_reduce(const float* __restrict__ x2d, const float* __restrict__ x1dnew) {
    int n = blockIdx.x >> 3, seg = blockIdx.x & 7;
    int tid = threadIdx.x, warp = tid >> 5, lane = tid & 31;
    __shared__ float4 fs[512];      // 8 KB
    __shared__ float wacc[8][4];
    const float4* f4 = (const float4*)x1dnew + n * 512;
    for (int q = tid; q < 512; q += 256) fs[q] = f4[q];
    __syncthreads();
    float ax = 0.f, ay = 0.f, az = 0.f, aw = 0.f;
    for (int r = 0; r < 8; r++) {
        int p = seg * 64 + warp * 8 + r;
        float4 fp = fs[p];
        const float4* row = (const float4*)x2d + ((size_t)n * 512 + p) * 512;
        #pragma unroll
        for (int j = 0; j < 16; j++) {
            int q = lane + (j << 5);
            float4 v  = row[q];
            float4 fq = fs[q];
            ax = fmaf(v.x * fq.x, fp.x, ax);
            ay = fmaf(v.y * fq.y, fp.y, ay);
            az = fmaf(v.z * fq.z, fp.z, az);
            aw = fmaf(v.w * fq.w, fp.w, aw);
        }
    }
    #pragma unroll
    for (int s = 16; s > 0; s >>= 1) {
        ax += __shfl_xor_sync(0xffffffff, ax, s);
        ay += __shfl_xor_sync(0xffffffff, ay, s);
        az += __shfl_xor_sync(0xffffffff, az, s);
        aw += __shfl_xor_sync(0xffffffff, aw, s);
    }
    if (lane == 0) { wacc[warp][0] = ax; wacc[warp][1] = ay; wacc[warp][2] = az; wacc[warp][3] = aw; }
    __syncthreads();
    if (tid < 4) {
        float s = 0.f;
        #pragma unroll
        for (int w = 0; w < 8; w++) s += wacc[w][tid];
        partN_s[n][seg][tid] = s;
    }
}

// ============================================================
// K7: gate -> per-n 4x4 M.  (R9 proven)
// ============================================================
__global__ void k_gate(const float* __restrict__ Wg, const float* __restrict__ bg,
                       const float* __restrict__ Wt) {
    int n = threadIdx.x;
    if (n >= BN) return;
    float a2[4] = {0.f, 0.f, 0.f, 0.f};
    #pragma unroll
    for (int s = 0; s < 8; s++)
        #pragma unroll
        for (int c = 0; c < 4; c++) a2[c] += partN_s[n][s][c];
    #pragma unroll
    for (int d = 0; d < 4; d++) {
        float pre = bg[d];
        #pragma unroll
        for (int c = 0; c < 4; c++) pre = fmaf(a2[c], Wg[d * 4 + c], pre);
        float gate = pre / (1.f + expf(-pre));
        #pragma unroll
        for (int c = 0; c < 4; c++) M2_s[n][d * 4 + c] = gate * Wt[d * 4 + c];
    }
}

// ============================================================
// K8: gated 4x4 matvec, r reversed (L2 tail), streaming stores. (R9)
// ============================================================
__global__ void __launch_bounds__(256, 4)
k_pass2(const float* __restrict__ x2d, float* __restrict__ x2dout) {
    int n = blockIdx.x >> 3, seg = blockIdx.x & 7;
    int tid = threadIdx.x, warp = tid >> 5, lane = tid & 31;
    float m[16];
    #pragma unroll
    for (int i = 0; i < 16; i++) m[i] = M2_s[n][i];
    for (int r = 7; r >= 0; r--) {
        int p = seg * 64 + warp * 8 + r;
        const float4* row  = (const float4*)x2d    + ((size_t)n * 512 + p) * 512;
        float4*       orow = (float4*)      x2dout + ((size_t)n * 512 + p) * 512;
        #pragma unroll
        for (int j = 0; j < 16; j++) {
            int q = lane + (j << 5);
            float4 v = row[q];
            float4 o;
            o.x = m[0]  * v.x + m[1]  * v.y + m[2]  * v.z + m[3]  * v.w;
            o.y = m[4]  * v.x + m[5]  * v.y + m[6]  * v.z + m[7]  * v.w;
            o.z = m[8]  * v.x + m[9]  * v.y + m[10] * v.z + m[11] * v.w;
            o.w = m[12] * v.x + m[13] * v.y + m[14] * v.z + m[15] * v.w;
            __stcs(&orow[q], o);   // evict-first: protect read lines in L2
        }
    }
}

// ============================================================
extern "C" void kernel_launch(void* const* d_in, const int* in_sizes, int n_in,
                              void* d_out, int out_size) {
    const float* x1d = (const float*)d_in[0];
    const float* x2d = (const float*)d_in[1];
    const float* W1  = (const float*)d_in[2];
    const float* b1  = (const float*)d_in[3];
    const float* W2  = (const float*)d_in[4];
    const float* b2  = (const float*)d_in[5];
    const float* Wie = (const float*)d_in[6];
    const float* Wt  = (const float*)d_in[7];
    const float* Wg  = (const float*)d_in[8];
    const float* bg  = (const float*)d_in[9];
    float* out = (float*)d_out;
    float* x1dnew = out;                       // [64, 2048]
    float* x2dnew = out + (size_t)BN * REP;    // [64, 512, 512, 4]

    k_norm_gauge<<<BN, 256>>>(x1d);
    k_bn<<<4, 128>>>();
    k_gemm<<<dim3(64, 9), 256>>>(W1, b1, 0, x2d, 0);   // swish + prefetch P=0
    k_gemm<<<dim3(64, 9), 256>>>(W2, b2, 1, x2d, 1);   // linear + prefetch P=1
    k_ielin<<<dim3(128, 17), 256>>>(Wie, x1dnew, x2d); // + prefetch P=2
    k_reduce<<<512, 256>>>(x2d, x1dnew);
    k_gate<<<1, 64>>>(Wg, bg, Wt);
    k_pass2<<<512, 256>>>(x2d, x2dnew);
}

// round 15
// speedup vs baseline: 1.1752x; 1.1752x over previous
#include <cuda_runtime.h>
#include <math.h>

// ---- static problem dims ----
#define BN      64      // batch (nodes)
#define NCL     128
#define NC      512     // total channels
#define REP     2048    // rep components
#define DD      512     // folded dim
#define NORM_EPS 1e-2f
#define BN_EPS   1e-5f

__device__ __constant__ int REP_OFF_C[4] = {0, 128, 512, 1152};

// ---- scratch (__device__ globals: allocation-free) ----
__device__ float g_s[BN * REP];      // gauge tensor
__device__ float norm_s[BN * NC];    // per-(l,channel) norms
__device__ float nbn_s[BN * NC];     // batchnormed norms
__device__ float h_s[BN * NC];       // MLP hidden
__device__ float n1_s[BN * NC];      // MLP out
__device__ float partN_s[BN][8][4];  // per-node per-segment bilinear partials

// ============================================================
// K1: per-node norms + gauge tensor.  One block per n.  (R9 proven)
// ============================================================
__global__ void k_norm_gauge(const float* __restrict__ x1d) {
    int n = blockIdx.x;
    __shared__ float xs[REP];   // 8 KB
    __shared__ float ns[NC];    // 2 KB
    const float* xr = x1d + n * REP;
    for (int i = threadIdx.x; i < REP; i += 256) xs[i] = xr[i];
    __syncthreads();
    for (int c = threadIdx.x; c < NC; c += 256) {
        int l = c >> 7, j = c & 127, off = REP_OFF_C[l], nm = 2 * l + 1;
        float s = 0.f;
        #pragma unroll 7
        for (int m = 0; m < nm; m++) { float v = xs[off + m * 128 + j]; s += v * v; }
        float nv = sqrtf(s);
        ns[c] = nv;
        norm_s[n * NC + c] = nv;
    }
    __syncthreads();
    for (int r = threadIdx.x; r < REP; r += 256) {
        int l = (r < 128) ? 0 : (r < 512) ? 1 : (r < 1152) ? 2 : 3;
        int c = l * 128 + ((r - REP_OFF_C[l]) & 127);
        g_s[n * REP + r] = xs[r] / (ns[c] + NORM_EPS);
    }
}

// ============================================================
// K2: batchnorm over batch axis. grid 4 x 128 threads.  (R9 proven)
// ============================================================
__global__ void k_bn() {
    int c = blockIdx.x * 128 + threadIdx.x;
    float mu = 0.f;
    #pragma unroll 8
    for (int n = 0; n < BN; n++) mu += norm_s[n * NC + c];
    mu *= (1.f / BN);
    float var = 0.f;
    #pragma unroll 8
    for (int n = 0; n < BN; n++) { float d = norm_s[n * NC + c] - mu; var += d * d; }
    var *= (1.f / BN);
    float inv = 1.f / sqrtf(var + BN_EPS);
    #pragma unroll 8
    for (int n = 0; n < BN; n++) nbn_s[n * NC + c] = (norm_s[n * NC + c] - mu) * inv;
}

// ============================================================
// K3/K4: [64,512] @ W^T + bias, optional swish — K-SPLIT version.
// 8 warps/block: warp w -> output o = blockIdx.x*4 + (w>>1),
// k-half = w&1 (256-wide half dot).  Per-warp critical path is
// half of R9's (8 W loads, 64 FMA, shfl tree); partials combined
// via smem.  Grid (128 o-blocks, 8 n-groups) = 1024 blocks.
// ============================================================
__global__ void k_gemm(const float* __restrict__ W, const float* __restrict__ bias, int which) {
    const float* X = which ? h_s : nbn_s;
    float* Y       = which ? n1_s : h_s;
    __shared__ float xs[512][12];   // 24 KB, transposed (12-pad, LDS.128-safe)
    __shared__ float part[8][8];    // per-warp partials
    int ng  = blockIdx.y * 8;
    int tid = threadIdx.x, warp = tid >> 5, lane = tid & 31;
    int o    = blockIdx.x * 4 + (warp >> 1);
    int half = warp & 1;
    for (int i = tid; i < 8 * 512; i += 256) {
        int j = i >> 9, k = i & 511;
        xs[k][j] = X[(ng + j) * NC + k];
    }
    __syncthreads();
    const float* wrow = W + o * NC + half * 256;
    float a0=0.f,a1=0.f,a2=0.f,a3=0.f,a4=0.f,a5=0.f,a6=0.f,a7=0.f;
    #pragma unroll
    for (int j = 0; j < 8; j++) {
        int k = half * 256 + lane + (j << 5);
        float w = wrow[lane + (j << 5)];
        float4 xa = *(const float4*)&xs[k][0];
        float4 xb = *(const float4*)&xs[k][4];
        a0 = fmaf(w, xa.x, a0);
        a1 = fmaf(w, xa.y, a1);
        a2 = fmaf(w, xa.z, a2);
        a3 = fmaf(w, xa.w, a3);
        a4 = fmaf(w, xb.x, a4);
        a5 = fmaf(w, xb.y, a5);
        a6 = fmaf(w, xb.z, a6);
        a7 = fmaf(w, xb.w, a7);
    }
    #pragma unroll
    for (int s = 16; s > 0; s >>= 1) {
        a0 += __shfl_xor_sync(0xffffffff, a0, s);
        a1 += __shfl_xor_sync(0xffffffff, a1, s);
        a2 += __shfl_xor_sync(0xffffffff, a2, s);
        a3 += __shfl_xor_sync(0xffffffff, a3, s);
        a4 += __shfl_xor_sync(0xffffffff, a4, s);
        a5 += __shfl_xor_sync(0xffffffff, a5, s);
        a6 += __shfl_xor_sync(0xffffffff, a6, s);
        a7 += __shfl_xor_sync(0xffffffff, a7, s);
    }
    if (lane == 0) {
        part[warp][0] = a0; part[warp][1] = a1; part[warp][2] = a2; part[warp][3] = a3;
        part[warp][4] = a4; part[warp][5] = a5; part[warp][6] = a6; part[warp][7] = a7;
    }
    __syncthreads();
    if (half == 0 && lane < 8) {
        float u = part[warp][lane] + part[warp + 1][lane] + bias[o];
        if (!which) u = u / (1.f + expf(-u));   // swish
        Y[(ng + lane) * NC + o] = u;
    }
}

// ============================================================
// K5: IELin fused with scalar_mul -> x1d_new (into d_out).  (R9 proven)
// ============================================================
__global__ void k_ielin(const float* __restrict__ Wie, float* __restrict__ x1dout) {
    __shared__ float gsT[128][12];  // 6 KB, transposed
    __shared__ int nrow[8], mrow[8];
    int rowbase = blockIdx.x * 8;
    int l, lbase;
    if (rowbase < 64)       { l = 0; lbase = 0; }
    else if (rowbase < 256) { l = 1; lbase = 64; }
    else if (rowbase < 576) { l = 2; lbase = 256; }
    else                    { l = 3; lbase = 576; }
    int nm = 2 * l + 1, off = REP_OFF_C[l];
    int tid = threadIdx.x, warp = tid >> 5, lane = tid & 31;
    if (tid < 8) {
        int rr = rowbase + tid - lbase;
        nrow[tid] = rr / nm;
        mrow[tid] = rr - nrow[tid] * nm;
    }
    __syncthreads();
    for (int idx = tid; idx < 8 * 128; idx += 256) {
        int j = idx >> 7, i = idx & 127;
        gsT[i][j] = g_s[nrow[j] * REP + off + mrow[j] * 128 + i];
    }
    __syncthreads();
    int o = blockIdx.y * 8 + warp;
    const float* wrow = Wie + (l * 128 + o) * 128;
    float a0=0.f,a1=0.f,a2=0.f,a3=0.f,a4=0.f,a5=0.f,a6=0.f,a7=0.f;
    #pragma unroll
    for (int j = 0; j < 4; j++) {
        int k = lane + (j << 5);
        float w = wrow[k];
        float4 ga = *(const float4*)&gsT[k][0];
        float4 gb = *(const float4*)&gsT[k][4];
        a0 = fmaf(w, ga.x, a0);
        a1 = fmaf(w, ga.y, a1);
        a2 = fmaf(w, ga.z, a2);
        a3 = fmaf(w, ga.w, a3);
        a4 = fmaf(w, gb.x, a4);
        a5 = fmaf(w, gb.y, a5);
        a6 = fmaf(w, gb.z, a6);
        a7 = fmaf(w, gb.w, a7);
    }
    #pragma unroll
    for (int s = 16; s > 0; s >>= 1) {
        a0 += __shfl_xor_sync(0xffffffff, a0, s);
        a1 += __shfl_xor_sync(0xffffffff, a1, s);
        a2 += __shfl_xor_sync(0xffffffff, a2, s);
        a3 += __shfl_xor_sync(0xffffffff, a3, s);
        a4 += __shfl_xor_sync(0xffffffff, a4, s);
        a5 += __shfl_xor_sync(0xffffffff, a5, s);
        a6 += __shfl_xor_sync(0xffffffff, a6, s);
        a7 += __shfl_xor_sync(0xffffffff, a7, s);
    }
    if (lane == 0) {
        float acc[8] = {a0, a1, a2, a3, a4, a5, a6, a7};
        #pragma unroll
        for (int j = 0; j < 8; j++) {
            int n = nrow[j];
            x1dout[n * REP + off + mrow[j] * 128 + o] =
                acc[j] * n1_s[n * NC + l * 128 + o];
        }
    }
}

// ============================================================
// K6: bilinear reduction.  (R9 proven: 512 blocks, 8 segs/node)
// ============================================================
__global__ void __launch_bounds__(256, 4)
k_reduce(const float* __restrict__ x2d, const float* __restrict__ x1dnew) {
    int n = blockIdx.x >> 3, seg = blockIdx.x & 7;
    int tid = threadIdx.x, warp = tid >> 5, lane = tid & 31;
    __shared__ float4 fs[512];      // 8 KB
    __shared__ float wacc[8][4];
    const float4* f4 = (const float4*)x1dnew + n * 512;
    for (int q = tid; q < 512; q += 256) fs[q] = f4[q];
    __syncthreads();
    float ax = 0.f, ay = 0.f, az = 0.f, aw = 0.f;
    for (int r = 0; r < 8; r++) {
        int p = seg * 64 + warp * 8 + r;
        float4 fp = fs[p];
        const float4* row = (const float4*)x2d + ((size_t)n * 512 + p) * 512;
        #pragma unroll
        for (int j = 0; j < 16; j++) {
            int q = lane + (j << 5);
            float4 v  = row[q];
            float4 fq = fs[q];
            ax = fmaf(v.x * fq.x, fp.x, ax);
            ay = fmaf(v.y * fq.y, fp.y, ay);
            az = fmaf(v.z * fq.z, fp.z, az);
            aw = fmaf(v.w * fq.w, fp.w, aw);
        }
    }
    #pragma unroll
    for (int s = 16; s > 0; s >>= 1) {
        ax += __shfl_xor_sync(0xffffffff, ax, s);
        ay += __shfl_xor_sync(0xffffffff, ay, s);
        az += __shfl_xor_sync(0xffffffff, az, s);
        aw += __shfl_xor_sync(0xffffffff, aw, s);
    }
    if (lane == 0) { wacc[warp][0] = ax; wacc[warp][1] = ay; wacc[warp][2] = az; wacc[warp][3] = aw; }
    __syncthreads();
    if (tid < 4) {
        float s = 0.f;
        #pragma unroll
        for (int w = 0; w < 8; w++) s += wacc[w][tid];
        partN_s[n][seg][tid] = s;
    }
}

// ============================================================
// K7: gated 4x4 matvec with gate computed in the prologue
// (per-block redundant, fixed-order deterministic sum; partN_s is
// complete at the kernel boundary).  r reversed (L2 tail) +
// streaming stores.  (R9 body + folded gate)
// ============================================================
__global__ void __launch_bounds__(256, 4)
k_pass2(const float* __restrict__ x2d, const float* __restrict__ Wg,
        const float* __restrict__ bg, const float* __restrict__ Wt,
        float* __restrict__ x2dout) {
    int n = blockIdx.x >> 3, seg = blockIdx.x & 7;
    int tid = threadIdx.x, warp = tid >> 5, lane = tid & 31;
    __shared__ float Msh[16];
    if (tid == 0) {
        float a2[4] = {0.f, 0.f, 0.f, 0.f};
        #pragma unroll
        for (int s = 0; s < 8; s++)
            #pragma unroll
            for (int c = 0; c < 4; c++) a2[c] += partN_s[n][s][c];
        #pragma unroll
        for (int d = 0; d < 4; d++) {
            float pre = bg[d];
            #pragma unroll
            for (int c = 0; c < 4; c++) pre = fmaf(a2[c], Wg[d * 4 + c], pre);
            float gate = pre / (1.f + expf(-pre));
            #pragma unroll
            for (int c = 0; c < 4; c++) Msh[d * 4 + c] = gate * Wt[d * 4 + c];
        }
    }
    __syncthreads();
    float m[16];
    #pragma unroll
    for (int i = 0; i < 16; i++) m[i] = Msh[i];
    for (int r = 7; r >= 0; r--) {
        int p = seg * 64 + warp * 8 + r;
        const float4* row  = (const float4*)x2d    + ((size_t)n * 512 + p) * 512;
        float4*       orow = (float4*)      x2dout + ((size_t)n * 512 + p) * 512;
        #pragma unroll
        for (int j = 0; j < 16; j++) {
            int q = lane + (j << 5);
            float4 v = row[q];
            float4 o;
            o.x = m[0]  * v.x + m[1]  * v.y + m[2]  * v.z + m[3]  * v.w;
            o.y = m[4]  * v.x + m[5]  * v.y + m[6]  * v.z + m[7]  * v.w;
            o.z = m[8]  * v.x + m[9]  * v.y + m[10] * v.z + m[11] * v.w;
            o.w = m[12] * v.x + m[13] * v.y + m[14] * v.z + m[15] * v.w;
            __stcs(&orow[q], o);   // evict-first
        }
    }
}

// ============================================================
extern "C" void kernel_launch(void* const* d_in, const int* in_sizes, int n_in,
                              void* d_out, int out_size) {
    const float* x1d = (const float*)d_in[0];
    const float* x2d = (const float*)d_in[1];
    const float* W1  = (const float*)d_in[2];
    const float* b1  = (const float*)d_in[3];
    const float* W2  = (const float*)d_in[4];
    const float* b2  = (const float*)d_in[5];
    const float* Wie = (const float*)d_in[6];
    const float* Wt  = (const float*)d_in[7];
    const float* Wg  = (const float*)d_in[8];
    const float* bg  = (const float*)d_in[9];
    float* out = (float*)d_out;
    float* x1dnew = out;                       // [64, 2048]
    float* x2dnew = out + (size_t)BN * REP;    // [64, 512, 512, 4]

    k_norm_gauge<<<BN, 256>>>(x1d);
    k_bn<<<4, 128>>>();
    k_gemm<<<dim3(128, 8), 256>>>(W1, b1, 0);  // swish, k-split
    k_gemm<<<dim3(128, 8), 256>>>(W2, b2, 1);  // linear, k-split
    k_ielin<<<dim3(128, 16), 256>>>(Wie, x1dnew);
    k_reduce<<<512, 256>>>(x2d, x1dnew);
    k_pass2<<<512, 256>>>(x2d, Wg, bg, Wt, x2dnew);
}

// round 16
// speedup vs baseline: 1.2021x; 1.0229x over previous
#include <cuda_runtime.h>
#include <math.h>

// ---- static problem dims ----
#define BN      64      // batch (nodes)
#define NCL     128
#define NC      512     // total channels
#define REP     2048    // rep components
#define DD      512     // folded dim
#define NORM_EPS 1e-2f
#define BN_EPS   1e-5f

__device__ __constant__ int REP_OFF_C[4] = {0, 128, 512, 1152};

// ---- scratch (__device__ globals: allocation-free) ----
__device__ float g_s[BN * REP];       // gauge tensor
__device__ float norm_s[BN * NC];     // per-(l,channel) norms
__device__ float nbn_s[BN * NC];      // batchnormed norms
__device__ float h_s[BN * NC];        // MLP hidden
__device__ float n1_s[BN * NC];       // MLP out
__device__ float partN_s[BN][16][4];  // per-node per-segment bilinear partials

// ============================================================
// K1: per-node norms + gauge tensor.  One block per n.  (R9 proven)
// ============================================================
__global__ void k_norm_gauge(const float* __restrict__ x1d) {
    int n = blockIdx.x;
    __shared__ float xs[REP];   // 8 KB
    __shared__ float ns[NC];    // 2 KB
    const float* xr = x1d + n * REP;
    for (int i = threadIdx.x; i < REP; i += 256) xs[i] = xr[i];
    __syncthreads();
    for (int c = threadIdx.x; c < NC; c += 256) {
        int l = c >> 7, j = c & 127, off = REP_OFF_C[l], nm = 2 * l + 1;
        float s = 0.f;
        #pragma unroll 7
        for (int m = 0; m < nm; m++) { float v = xs[off + m * 128 + j]; s += v * v; }
        float nv = sqrtf(s);
        ns[c] = nv;
        norm_s[n * NC + c] = nv;
    }
    __syncthreads();
    for (int r = threadIdx.x; r < REP; r += 256) {
        int l = (r < 128) ? 0 : (r < 512) ? 1 : (r < 1152) ? 2 : 3;
        int c = l * 128 + ((r - REP_OFF_C[l]) & 127);
        g_s[n * REP + r] = xs[r] / (ns[c] + NORM_EPS);
    }
}

// ============================================================
// K2: batchnorm over batch axis. grid 4 x 128 threads.  (R9 proven)
// ============================================================
__global__ void k_bn() {
    int c = blockIdx.x * 128 + threadIdx.x;
    float mu = 0.f;
    #pragma unroll 8
    for (int n = 0; n < BN; n++) mu += norm_s[n * NC + c];
    mu *= (1.f / BN);
    float var = 0.f;
    #pragma unroll 8
    for (int n = 0; n < BN; n++) { float d = norm_s[n * NC + c] - mu; var += d * d; }
    var *= (1.f / BN);
    float inv = 1.f / sqrtf(var + BN_EPS);
    #pragma unroll 8
    for (int n = 0; n < BN; n++) nbn_s[n * NC + c] = (norm_s[n * NC + c] - mu) * inv;
}

// ============================================================
// K3/K4: [64,512] @ W^T + bias, optional swish.  (R9 proven exact)
// ============================================================
__global__ void k_gemm(const float* __restrict__ W, const float* __restrict__ bias, int which) {
    const float* X = which ? h_s : nbn_s;
    float* Y       = which ? n1_s : h_s;
    __shared__ float xs[512][12];   // 24 KB, transposed
    int ng  = blockIdx.y * 8;
    int tid = threadIdx.x, warp = tid >> 5, lane = tid & 31;
    int o = blockIdx.x * 8 + warp;
    for (int i = tid; i < 8 * 512; i += 256) {
        int j = i >> 9, k = i & 511;
        xs[k][j] = X[(ng + j) * NC + k];
    }
    __syncthreads();
    const float* wrow = W + o * NC;
    float a0=0.f,a1=0.f,a2=0.f,a3=0.f,a4=0.f,a5=0.f,a6=0.f,a7=0.f;
    #pragma unroll
    for (int j = 0; j < 16; j++) {
        int k = lane + (j << 5);
        float w = wrow[k];
        float4 xa = *(const float4*)&xs[k][0];
        float4 xb = *(const float4*)&xs[k][4];
        a0 = fmaf(w, xa.x, a0);
        a1 = fmaf(w, xa.y, a1);
        a2 = fmaf(w, xa.z, a2);
        a3 = fmaf(w, xa.w, a3);
        a4 = fmaf(w, xb.x, a4);
        a5 = fmaf(w, xb.y, a5);
        a6 = fmaf(w, xb.z, a6);
        a7 = fmaf(w, xb.w, a7);
    }
    #pragma unroll
    for (int s = 16; s > 0; s >>= 1) {
        a0 += __shfl_xor_sync(0xffffffff, a0, s);
        a1 += __shfl_xor_sync(0xffffffff, a1, s);
        a2 += __shfl_xor_sync(0xffffffff, a2, s);
        a3 += __shfl_xor_sync(0xffffffff, a3, s);
        a4 += __shfl_xor_sync(0xffffffff, a4, s);
        a5 += __shfl_xor_sync(0xffffffff, a5, s);
        a6 += __shfl_xor_sync(0xffffffff, a6, s);
        a7 += __shfl_xor_sync(0xffffffff, a7, s);
    }
    if (lane == 0) {
        float b = bias[o];
        float v[8] = {a0+b, a1+b, a2+b, a3+b, a4+b, a5+b, a6+b, a7+b};
        #pragma unroll
        for (int j = 0; j < 8; j++) {
            float u = v[j];
            if (!which) u = u / (1.f + expf(-u));   // swish
            Y[(ng + j) * NC + o] = u;
        }
    }
}

// ============================================================
// K5: IELin fused with scalar_mul -> x1d_new (into d_out).  (R9 proven)
// ============================================================
__global__ void k_ielin(const float* __restrict__ Wie, float* __restrict__ x1dout) {
    __shared__ float gsT[128][12];  // 6 KB, transposed
    __shared__ int nrow[8], mrow[8];
    int rowbase = blockIdx.x * 8;
    int l, lbase;
    if (rowbase < 64)       { l = 0; lbase = 0; }
    else if (rowbase < 256) { l = 1; lbase = 64; }
    else if (rowbase < 576) { l = 2; lbase = 256; }
    else                    { l = 3; lbase = 576; }
    int nm = 2 * l + 1, off = REP_OFF_C[l];
    int tid = threadIdx.x, warp = tid >> 5, lane = tid & 31;
    if (tid < 8) {
        int rr = rowbase + tid - lbase;
        nrow[tid] = rr / nm;
        mrow[tid] = rr - nrow[tid] * nm;
    }
    __syncthreads();
    for (int idx = tid; idx < 8 * 128; idx += 256) {
        int j = idx >> 7, i = idx & 127;
        gsT[i][j] = g_s[nrow[j] * REP + off + mrow[j] * 128 + i];
    }
    __syncthreads();
    int o = blockIdx.y * 8 + warp;
    const float* wrow = Wie + (l * 128 + o) * 128;
    float a0=0.f,a1=0.f,a2=0.f,a3=0.f,a4=0.f,a5=0.f,a6=0.f,a7=0.f;
    #pragma unroll
    for (int j = 0; j < 4; j++) {
        int k = lane + (j << 5);
        float w = wrow[k];
        float4 ga = *(const float4*)&gsT[k][0];
        float4 gb = *(const float4*)&gsT[k][4];
        a0 = fmaf(w, ga.x, a0);
        a1 = fmaf(w, ga.y, a1);
        a2 = fmaf(w, ga.z, a2);
        a3 = fmaf(w, ga.w, a3);
        a4 = fmaf(w, gb.x, a4);
        a5 = fmaf(w, gb.y, a5);
        a6 = fmaf(w, gb.z, a6);
        a7 = fmaf(w, gb.w, a7);
    }
    #pragma unroll
    for (int s = 16; s > 0; s >>= 1) {
        a0 += __shfl_xor_sync(0xffffffff, a0, s);
        a1 += __shfl_xor_sync(0xffffffff, a1, s);
        a2 += __shfl_xor_sync(0xffffffff, a2, s);
        a3 += __shfl_xor_sync(0xffffffff, a3, s);
        a4 += __shfl_xor_sync(0xffffffff, a4, s);
        a5 += __shfl_xor_sync(0xffffffff, a5, s);
        a6 += __shfl_xor_sync(0xffffffff, a6, s);
        a7 += __shfl_xor_sync(0xffffffff, a7, s);
    }
    if (lane == 0) {
        float acc[8] = {a0, a1, a2, a3, a4, a5, a6, a7};
        #pragma unroll
        for (int j = 0; j < 8; j++) {
            int n = nrow[j];
            x1dout[n * REP + off + mrow[j] * 128 + o] =
                acc[j] * n1_s[n * NC + l * 128 + o];
        }
    }
}

// ============================================================
// K6: bilinear reduction.  1024 blocks (n = bid>>4, seg = bid&15),
// 32 rows each (warp owns 4, r ascending) -> smaller straggler tail.
// ============================================================
__global__ void __launch_bounds__(256)
k_reduce(const float* __restrict__ x2d, const float* __restrict__ x1dnew) {
    int n = blockIdx.x >> 4, seg = blockIdx.x & 15;
    int tid = threadIdx.x, warp = tid >> 5, lane = tid & 31;
    __shared__ float4 fs[512];      // 8 KB
    __shared__ float wacc[8][4];
    const float4* f4 = (const float4*)x1dnew + n * 512;
    for (int q = tid; q < 512; q += 256) fs[q] = f4[q];
    __syncthreads();
    float ax = 0.f, ay = 0.f, az = 0.f, aw = 0.f;
    for (int r = 0; r < 4; r++) {
        int p = seg * 32 + warp * 4 + r;
        float4 fp = fs[p];
        const float4* row = (const float4*)x2d + ((size_t)n * 512 + p) * 512;
        #pragma unroll
        for (int j = 0; j < 16; j++) {
            int q = lane + (j << 5);
            float4 v  = row[q];
            float4 fq = fs[q];
            ax = fmaf(v.x * fq.x, fp.x, ax);
            ay = fmaf(v.y * fq.y, fp.y, ay);
            az = fmaf(v.z * fq.z, fp.z, az);
            aw = fmaf(v.w * fq.w, fp.w, aw);
        }
    }
    #pragma unroll
    for (int s = 16; s > 0; s >>= 1) {
        ax += __shfl_xor_sync(0xffffffff, ax, s);
        ay += __shfl_xor_sync(0xffffffff, ay, s);
        az += __shfl_xor_sync(0xffffffff, az, s);
        aw += __shfl_xor_sync(0xffffffff, aw, s);
    }
    if (lane == 0) { wacc[warp][0] = ax; wacc[warp][1] = ay; wacc[warp][2] = az; wacc[warp][3] = aw; }
    __syncthreads();
    if (tid < 4) {
        float s = 0.f;
        #pragma unroll
        for (int w = 0; w < 8; w++) s += wacc[w][tid];
        partN_s[n][seg][tid] = s;
    }
}

// ============================================================
// K7: gated 4x4 matvec; gate computed in prologue (fixed-order
// deterministic sum; partN_s complete at kernel boundary).
// 1024 blocks, r reversed (L2 tail), streaming stores.
// ============================================================
__global__ void __launch_bounds__(256)
k_pass2(const float* __restrict__ x2d, const float* __restrict__ Wg,
        const float* __restrict__ bg, const float* __restrict__ Wt,
        float* __restrict__ x2dout) {
    int n = blockIdx.x >> 4, seg = blockIdx.x & 15;
    int tid = threadIdx.x, warp = tid >> 5, lane = tid & 31;
    __shared__ float Msh[16];
    if (tid == 0) {
        float a2[4] = {0.f, 0.f, 0.f, 0.f};
        #pragma unroll
        for (int s = 0; s < 16; s++)
            #pragma unroll
            for (int c = 0; c < 4; c++) a2[c] += partN_s[n][s][c];
        #pragma unroll
        for (int d = 0; d < 4; d++) {
            float pre = bg[d];
            #pragma unroll
            for (int c = 0; c < 4; c++) pre = fmaf(a2[c], Wg[d * 4 + c], pre);
            float gate = pre / (1.f + expf(-pre));
            #pragma unroll
            for (int c = 0; c < 4; c++) Msh[d * 4 + c] = gate * Wt[d * 4 + c];
        }
    }
    __syncthreads();
    float m[16];
    #pragma unroll
    for (int i = 0; i < 16; i++) m[i] = Msh[i];
    for (int r = 3; r >= 0; r--) {
        int p = seg * 32 + warp * 4 + r;
        const float4* row  = (const float4*)x2d    + ((size_t)n * 512 + p) * 512;
        float4*       orow = (float4*)      x2dout + ((size_t)n * 512 + p) * 512;
        #pragma unroll
        for (int j = 0; j < 16; j++) {
            int q = lane + (j << 5);
            float4 v = row[q];
            float4 o;
            o.x = m[0]  * v.x + m[1]  * v.y + m[2]  * v.z + m[3]  * v.w;
            o.y = m[4]  * v.x + m[5]  * v.y + m[6]  * v.z + m[7]  * v.w;
            o.z = m[8]  * v.x + m[9]  * v.y + m[10] * v.z + m[11] * v.w;
            o.w = m[12] * v.x + m[13] * v.y + m[14] * v.z + m[15] * v.w;
            __stcs(&orow[q], o);   // evict-first
        }
    }
}

// ============================================================
extern "C" void kernel_launch(void* const* d_in, const int* in_sizes, int n_in,
                              void* d_out, int out_size) {
    const float* x1d = (const float*)d_in[0];
    const float* x2d = (const float*)d_in[1];
    const float* W1  = (const float*)d_in[2];
    const float* b1  = (const float*)d_in[3];
    const float* W2  = (const float*)d_in[4];
    const float* b2  = (const float*)d_in[5];
    const float* Wie = (const float*)d_in[6];
    const float* Wt  = (const float*)d_in[7];
    const float* Wg  = (const float*)d_in[8];
    const float* bg  = (const float*)d_in[9];
    float* out = (float*)d_out;
    float* x1dnew = out;                       // [64, 2048]
    float* x2dnew = out + (size_t)BN * REP;    // [64, 512, 512, 4]

    k_norm_gauge<<<BN, 256>>>(x1d);
    k_bn<<<4, 128>>>();
    k_gemm<<<dim3(64, 8), 256>>>(W1, b1, 0);   // swish
    k_gemm<<<dim3(64, 8), 256>>>(W2, b2, 1);   // linear
    k_ielin<<<dim3(128, 16), 256>>>(Wie, x1dnew);
    k_reduce<<<1024, 256>>>(x2d, x1dnew);
    k_pass2<<<1024, 256>>>(x2d, Wg, bg, Wt, x2dnew);
}

// round 17
// speedup vs baseline: 1.2281x; 1.0216x over previous
#include <cuda_runtime.h>
#include <math.h>

// ---- static problem dims ----
#define BN      64      // batch (nodes)
#define NCL     128
#define NC      512     // total channels
#define REP     2048    // rep components
#define DD      512     // folded dim
#define NORM_EPS 1e-2f
#define BN_EPS   1e-5f

__device__ __constant__ int REP_OFF_C[4] = {0, 128, 512, 1152};

// ---- scratch (__device__ globals: allocation-free) ----
__device__ float g_s[BN * REP];       // gauge tensor
__device__ float norm_s[BN * NC];     // per-(l,channel) norms
__device__ float nbn_s[BN * NC];      // batchnormed norms
__device__ float h_s[BN * NC];        // MLP hidden
__device__ float n1_s[BN * NC];       // MLP out
__device__ float partN_s[BN][16][4];  // per-node per-segment bilinear partials

// ============================================================
// K1: per-node norms + gauge tensor.  One block per n.  (proven)
// ============================================================
__global__ void k_norm_gauge(const float* __restrict__ x1d) {
    int n = blockIdx.x;
    __shared__ float xs[REP];   // 8 KB
    __shared__ float ns[NC];    // 2 KB
    const float* xr = x1d + n * REP;
    for (int i = threadIdx.x; i < REP; i += 256) xs[i] = xr[i];
    __syncthreads();
    for (int c = threadIdx.x; c < NC; c += 256) {
        int l = c >> 7, j = c & 127, off = REP_OFF_C[l], nm = 2 * l + 1;
        float s = 0.f;
        #pragma unroll 7
        for (int m = 0; m < nm; m++) { float v = xs[off + m * 128 + j]; s += v * v; }
        float nv = sqrtf(s);
        ns[c] = nv;
        norm_s[n * NC + c] = nv;
    }
    __syncthreads();
    for (int r = threadIdx.x; r < REP; r += 256) {
        int l = (r < 128) ? 0 : (r < 512) ? 1 : (r < 1152) ? 2 : 3;
        int c = l * 128 + ((r - REP_OFF_C[l]) & 127);
        g_s[n * REP + r] = xs[r] / (ns[c] + NORM_EPS);
    }
}

// ============================================================
// K2: batchnorm over batch axis. grid 4 x 128 threads.  (proven)
// ============================================================
__global__ void k_bn() {
    int c = blockIdx.x * 128 + threadIdx.x;
    float mu = 0.f;
    #pragma unroll 8
    for (int n = 0; n < BN; n++) mu += norm_s[n * NC + c];
    mu *= (1.f / BN);
    float var = 0.f;
    #pragma unroll 8
    for (int n = 0; n < BN; n++) { float d = norm_s[n * NC + c] - mu; var += d * d; }
    var *= (1.f / BN);
    float inv = 1.f / sqrtf(var + BN_EPS);
    #pragma unroll 8
    for (int n = 0; n < BN; n++) nbn_s[n * NC + c] = (norm_s[n * NC + c] - mu) * inv;
}

// ============================================================
// K3/K4: [64,512] @ W^T + bias, optional swish.  (proven exact)
// ============================================================
__global__ void k_gemm(const float* __restrict__ W, const float* __restrict__ bias, int which) {
    const float* X = which ? h_s : nbn_s;
    float* Y       = which ? n1_s : h_s;
    __shared__ float xs[512][12];   // 24 KB, transposed
    int ng  = blockIdx.y * 8;
    int tid = threadIdx.x, warp = tid >> 5, lane = tid & 31;
    int o = blockIdx.x * 8 + warp;
    for (int i = tid; i < 8 * 512; i += 256) {
        int j = i >> 9, k = i & 511;
        xs[k][j] = X[(ng + j) * NC + k];
    }
    __syncthreads();
    const float* wrow = W + o * NC;
    float a0=0.f,a1=0.f,a2=0.f,a3=0.f,a4=0.f,a5=0.f,a6=0.f,a7=0.f;
    #pragma unroll
    for (int j = 0; j < 16; j++) {
        int k = lane + (j << 5);
        float w = wrow[k];
        float4 xa = *(const float4*)&xs[k][0];
        float4 xb = *(const float4*)&xs[k][4];
        a0 = fmaf(w, xa.x, a0);
        a1 = fmaf(w, xa.y, a1);
        a2 = fmaf(w, xa.z, a2);
        a3 = fmaf(w, xa.w, a3);
        a4 = fmaf(w, xb.x, a4);
        a5 = fmaf(w, xb.y, a5);
        a6 = fmaf(w, xb.z, a6);
        a7 = fmaf(w, xb.w, a7);
    }
    #pragma unroll
    for (int s = 16; s > 0; s >>= 1) {
        a0 += __shfl_xor_sync(0xffffffff, a0, s);
        a1 += __shfl_xor_sync(0xffffffff, a1, s);
        a2 += __shfl_xor_sync(0xffffffff, a2, s);
        a3 += __shfl_xor_sync(0xffffffff, a3, s);
        a4 += __shfl_xor_sync(0xffffffff, a4, s);
        a5 += __shfl_xor_sync(0xffffffff, a5, s);
        a6 += __shfl_xor_sync(0xffffffff, a6, s);
        a7 += __shfl_xor_sync(0xffffffff, a7, s);
    }
    if (lane == 0) {
        float b = bias[o];
        float v[8] = {a0+b, a1+b, a2+b, a3+b, a4+b, a5+b, a6+b, a7+b};
        #pragma unroll
        for (int j = 0; j < 8; j++) {
            float u = v[j];
            if (!which) u = u / (1.f + expf(-u));   // swish
            Y[(ng + j) * NC + o] = u;
        }
    }
}

// ============================================================
// K5: IELin fused with scalar_mul -> x1d_new (into d_out).  (proven)
// ============================================================
__global__ void k_ielin(const float* __restrict__ Wie, float* __restrict__ x1dout) {
    __shared__ float gsT[128][12];  // 6 KB, transposed
    __shared__ int nrow[8], mrow[8];
    int rowbase = blockIdx.x * 8;
    int l, lbase;
    if (rowbase < 64)       { l = 0; lbase = 0; }
    else if (rowbase < 256) { l = 1; lbase = 64; }
    else if (rowbase < 576) { l = 2; lbase = 256; }
    else                    { l = 3; lbase = 576; }
    int nm = 2 * l + 1, off = REP_OFF_C[l];
    int tid = threadIdx.x, warp = tid >> 5, lane = tid & 31;
    if (tid < 8) {
        int rr = rowbase + tid - lbase;
        nrow[tid] = rr / nm;
        mrow[tid] = rr - nrow[tid] * nm;
    }
    __syncthreads();
    for (int idx = tid; idx < 8 * 128; idx += 256) {
        int j = idx >> 7, i = idx & 127;
        gsT[i][j] = g_s[nrow[j] * REP + off + mrow[j] * 128 + i];
    }
    __syncthreads();
    int o = blockIdx.y * 8 + warp;
    const float* wrow = Wie + (l * 128 + o) * 128;
    float a0=0.f,a1=0.f,a2=0.f,a3=0.f,a4=0.f,a5=0.f,a6=0.f,a7=0.f;
    #pragma unroll
    for (int j = 0; j < 4; j++) {
        int k = lane + (j << 5);
        float w = wrow[k];
        float4 ga = *(const float4*)&gsT[k][0];
        float4 gb = *(const float4*)&gsT[k][4];
        a0 = fmaf(w, ga.x, a0);
        a1 = fmaf(w, ga.y, a1);
        a2 = fmaf(w, ga.z, a2);
        a3 = fmaf(w, ga.w, a3);
        a4 = fmaf(w, gb.x, a4);
        a5 = fmaf(w, gb.y, a5);
        a6 = fmaf(w, gb.z, a6);
        a7 = fmaf(w, gb.w, a7);
    }
    #pragma unroll
    for (int s = 16; s > 0; s >>= 1) {
        a0 += __shfl_xor_sync(0xffffffff, a0, s);
        a1 += __shfl_xor_sync(0xffffffff, a1, s);
        a2 += __shfl_xor_sync(0xffffffff, a2, s);
        a3 += __shfl_xor_sync(0xffffffff, a3, s);
        a4 += __shfl_xor_sync(0xffffffff, a4, s);
        a5 += __shfl_xor_sync(0xffffffff, a5, s);
        a6 += __shfl_xor_sync(0xffffffff, a6, s);
        a7 += __shfl_xor_sync(0xffffffff, a7, s);
    }
    if (lane == 0) {
        float acc[8] = {a0, a1, a2, a3, a4, a5, a6, a7};
        #pragma unroll
        for (int j = 0; j < 8; j++) {
            int n = nrow[j];
            x1dout[n * REP + off + mrow[j] * 128 + o] =
                acc[j] * n1_s[n * NC + l * 128 + o];
        }
    }
}

// ============================================================
// K6: bilinear reduction — LOOP-INTERCHANGED.
// 1024 blocks (n = bid>>4, seg = bid&15), warp owns 4 rows.
// fp[0..3] hoisted to registers; inner j-loop loads fq ONCE per
// q-chunk (16 LDS.128/thread vs 64) and 4 independent row loads
// -> all 64 LDGs exposed for front-batching (high MLP).
// ============================================================
__global__ void __launch_bounds__(256)
k_reduce(const float* __restrict__ x2d, const float* __restrict__ x1dnew) {
    int n = blockIdx.x >> 4, seg = blockIdx.x & 15;
    int tid = threadIdx.x, warp = tid >> 5, lane = tid & 31;
    __shared__ float4 fs[512];      // 8 KB
    __shared__ float wacc[8][4];
    const float4* f4 = (const float4*)x1dnew + n * 512;
    for (int q = tid; q < 512; q += 256) fs[q] = f4[q];
    __syncthreads();
    int p0 = seg * 32 + warp * 4;
    float4 fp0 = fs[p0 + 0];
    float4 fp1 = fs[p0 + 1];
    float4 fp2 = fs[p0 + 2];
    float4 fp3 = fs[p0 + 3];
    const float4* row0 = (const float4*)x2d + ((size_t)n * 512 + p0 + 0) * 512;
    const float4* row1 = (const float4*)x2d + ((size_t)n * 512 + p0 + 1) * 512;
    const float4* row2 = (const float4*)x2d + ((size_t)n * 512 + p0 + 2) * 512;
    const float4* row3 = (const float4*)x2d + ((size_t)n * 512 + p0 + 3) * 512;
    float ax = 0.f, ay = 0.f, az = 0.f, aw = 0.f;
    #pragma unroll
    for (int j = 0; j < 16; j++) {
        int q = lane + (j << 5);
        float4 fq = fs[q];
        float4 v0 = row0[q];
        float4 v1 = row1[q];
        float4 v2 = row2[q];
        float4 v3 = row3[q];
        float tx = v0.x * fp0.x; tx = fmaf(v1.x, fp1.x, tx); tx = fmaf(v2.x, fp2.x, tx); tx = fmaf(v3.x, fp3.x, tx);
        float ty = v0.y * fp0.y; ty = fmaf(v1.y, fp1.y, ty); ty = fmaf(v2.y, fp2.y, ty); ty = fmaf(v3.y, fp3.y, ty);
        float tz = v0.z * fp0.z; tz = fmaf(v1.z, fp1.z, tz); tz = fmaf(v2.z, fp2.z, tz); tz = fmaf(v3.z, fp3.z, tz);
        float tw = v0.w * fp0.w; tw = fmaf(v1.w, fp1.w, tw); tw = fmaf(v2.w, fp2.w, tw); tw = fmaf(v3.w, fp3.w, tw);
        ax = fmaf(tx, fq.x, ax);
        ay = fmaf(ty, fq.y, ay);
        az = fmaf(tz, fq.z, az);
        aw = fmaf(tw, fq.w, aw);
    }
    #pragma unroll
    for (int s = 16; s > 0; s >>= 1) {
        ax += __shfl_xor_sync(0xffffffff, ax, s);
        ay += __shfl_xor_sync(0xffffffff, ay, s);
        az += __shfl_xor_sync(0xffffffff, az, s);
        aw += __shfl_xor_sync(0xffffffff, aw, s);
    }
    if (lane == 0) { wacc[warp][0] = ax; wacc[warp][1] = ay; wacc[warp][2] = az; wacc[warp][3] = aw; }
    __syncthreads();
    if (tid < 4) {
        float s = 0.f;
        #pragma unroll
        for (int w = 0; w < 8; w++) s += wacc[w][tid];
        partN_s[n][seg][tid] = s;
    }
}

// ============================================================
// K7: gated 4x4 matvec; gate computed in prologue (fixed-order
// deterministic sum).  1024 blocks, r reversed, streaming stores.
// ============================================================
__global__ void __launch_bounds__(256)
k_pass2(const float* __restrict__ x2d, const float* __restrict__ Wg,
        const float* __restrict__ bg, const float* __restrict__ Wt,
        float* __restrict__ x2dout) {
    int n = blockIdx.x >> 4, seg = blockIdx.x & 15;
    int tid = threadIdx.x, warp = tid >> 5, lane = tid & 31;
    __shared__ float Msh[16];
    if (tid == 0) {
        float a2[4] = {0.f, 0.f, 0.f, 0.f};
        #pragma unroll
        for (int s = 0; s < 16; s++)
            #pragma unroll
            for (int c = 0; c < 4; c++) a2[c] += partN_s[n][s][c];
        #pragma unroll
        for (int d = 0; d < 4; d++) {
            float pre = bg[d];
            #pragma unroll
            for (int c = 0; c < 4; c++) pre = fmaf(a2[c], Wg[d * 4 + c], pre);
            float gate = pre / (1.f + expf(-pre));
            #pragma unroll
            for (int c = 0; c < 4; c++) Msh[d * 4 + c] = gate * Wt[d * 4 + c];
        }
    }
    __syncthreads();
    float m[16];
    #pragma unroll
    for (int i = 0; i < 16; i++) m[i] = Msh[i];
    for (int r = 3; r >= 0; r--) {
        int p = seg * 32 + warp * 4 + r;
        const float4* row  = (const float4*)x2d    + ((size_t)n * 512 + p) * 512;
        float4*       orow = (float4*)      x2dout + ((size_t)n * 512 + p) * 512;
        #pragma unroll
        for (int j = 0; j < 16; j++) {
            int q = lane + (j << 5);
            float4 v = row[q];
            float4 o;
            o.x = m[0]  * v.x + m[1]  * v.y + m[2]  * v.z + m[3]  * v.w;
            o.y = m[4]  * v.x + m[5]  * v.y + m[6]  * v.z + m[7]  * v.w;
            o.z = m[8]  * v.x + m[9]  * v.y + m[10] * v.z + m[11] * v.w;
            o.w = m[12] * v.x + m[13] * v.y + m[14] * v.z + m[15] * v.w;
            __stcs(&orow[q], o);   // evict-first
        }
    }
}

// ============================================================
extern "C" void kernel_launch(void* const* d_in, const int* in_sizes, int n_in,
                              void* d_out, int out_size) {
    const float* x1d = (const float*)d_in[0];
    const float* x2d = (const float*)d_in[1];
    const float* W1  = (const float*)d_in[2];
    const float* b1  = (const float*)d_in[3];
    const float* W2  = (const float*)d_in[4];
    const float* b2  = (const float*)d_in[5];
    const float* Wie = (const float*)d_in[6];
    const float* Wt  = (const float*)d_in[7];
    const float* Wg  = (const float*)d_in[8];
    const float* bg  = (const float*)d_in[9];
    float* out = (float*)d_out;
    float* x1dnew = out;                       // [64, 2048]
    float* x2dnew = out + (size_t)BN * REP;    // [64, 512, 512, 4]

    k_norm_gauge<<<BN, 256>>>(x1d);
    k_bn<<<4, 128>>>();
    k_gemm<<<dim3(64, 8), 256>>>(W1, b1, 0);   // swish
    k_gemm<<<dim3(64, 8), 256>>>(W2, b2, 1);   // linear
    k_ielin<<<dim3(128, 16), 256>>>(Wie, x1dnew);
    k_reduce<<<1024, 256>>>(x2d, x1dnew);
    k_pass2<<<1024, 256>>>(x2d, Wg, bg, Wt, x2dnew);
}